// round 6
// baseline (speedup 1.0000x reference)
#include <cuda_runtime.h>
#include <math.h>

// ---------------------------------------------------------------------------
// NB regression log-posterior. 3 launches:
//  k_perg : lgamma tables via recurrence (1 lgammaf/gene), priors -> d_part
//  k_rowA : gene-chunked single-pass  s_n = sum(Y[n,:]) and sumexp(mu+X beta)
//  k_main : per-block a_n recompute + 20.5M-element NB log-lik,
//           2 genes x 4 rows per iteration (8-deep load pipeline),
//           last-block deterministic final reduction.
// ---------------------------------------------------------------------------

#define GMAX  20480
#define NMAX  4096
#define NPART 4096
#define TN    32       // rows per k_main block
#define RN    8        // rows per k_rowA block
#define GS    8        // gene chunks in k_rowA

__device__ float  d_r[GMAX];
__device__ float  d_c[GMAX];
__device__ float  d_lft[512];
__device__ float  d_small[8 * GMAX];     // [y][g] : lgamma(y+r)-lgamma(y+1)
__device__ float  d_sp[NMAX * GS];       // library-size partials [n][chunk]
__device__ float  d_ep[NMAX * GS];       // sumexp partials       [n][chunk]
__device__ double d_part[NPART];
__device__ int    d_cnt = 0;

__device__ __forceinline__ float frcp_approx(float x) {
    float r; asm("rcp.approx.f32 %0, %1;" : "=f"(r) : "f"(x)); return r;
}

__device__ __forceinline__ double warp_red_d(double v) {
    #pragma unroll
    for (int o = 16; o; o >>= 1) v += __shfl_down_sync(0xffffffffu, v, o);
    return v;
}

// -------------------- kernel 1: tables + per-gene precompute + priors ------
__global__ __launch_bounds__(128) void k_perg(
        const float* __restrict__ mu, const float* __restrict__ beta,
        const float* __restrict__ phi, int G, int P) {
    __shared__ double sw[4];
    int g = blockIdx.x * 128 + threadIdx.x;
    if (g < 512) d_lft[g] = lgammaf((float)g + 1.0f);
    double loc = 0.0;
    if (g < G) {
        float ph = phi[g];
        float sp = fmaxf(ph, 0.0f) + log1pf(expf(-fabsf(ph)));  // softplus
        float r  = 1.0f / sp;
        d_r[g] = r;
        float lg_r = lgammaf(r);
        d_c[g] = r * logf(r) - lg_r;
        // lgamma(y+1) for y=0..7, exact constants
        const float LFT[8] = {0.0f, 0.0f, 0.6931471805599453f, 1.791759469228055f,
                              3.1780538303479458f, 4.787491742782046f,
                              6.579251212010101f, 8.525161361065415f};
        float acc = lg_r;                       // lgamma(0+r)
        #pragma unroll
        for (int y = 0; y < 8; y++) {
            d_small[y * G + g] = acc - LFT[y];
            acc += __logf(r + (float)y);        // -> lgamma(y+1+r)
        }
        const float C2 = -1.6120857137646180f;  // -0.5*log(2*pi*4)
        float m  = mu[g];
        float pr = C2 - m * m * 0.125f;         // normal prior on mu
        for (int p = 0; p < P; p++) {           // normal prior on beta
            float b = beta[p * G + g];
            pr += C2 - b * b * 0.125f;
        }
        pr += logf(sp) - sp;                    // gamma(2,1) prior: log x - x
        loc = (double)pr;
    }
    double w = warp_red_d(loc);
    int lid = threadIdx.x & 31, wid = threadIdx.x >> 5;
    if (lid == 0) sw[wid] = w;
    __syncthreads();
    if (wid == 0) {
        double v = (lid < 4) ? sw[lid] : 0.0;
        v = warp_red_d(v);
        if (lid == 0) d_part[blockIdx.x] = v;
    }
}

// -------------------- kernel 2: chunked library-size + sumexp partials -----
__global__ __launch_bounds__(256) void k_rowA(
        const float* __restrict__ X, const float* __restrict__ Y,
        const float* __restrict__ mu, const float* __restrict__ beta, int G) {
    __shared__ float xs[RN][4];
    __shared__ float red[8][2 * RN];
    int chunk = blockIdx.x;
    int L  = (G + GS - 1) / GS;
    int c0 = chunk * L;
    int c1 = min(c0 + L, G);
    int n0 = blockIdx.y * RN;
    int t  = threadIdx.x;
    if (t < RN * 4) ((float*)xs)[t] = X[n0 * 4 + t];
    __syncthreads();

    float s[RN], e[RN];
    #pragma unroll
    for (int i = 0; i < RN; i++) { s[i] = 0.0f; e[i] = 0.0f; }

    const float* ybase = Y + (size_t)n0 * G;
    for (int g = c0 + t; g < c1; g += 256) {
        float m  = mu[g];
        float b0 = beta[g];
        float b1 = beta[G + g];
        float b2 = beta[2 * G + g];
        float b3 = beta[3 * G + g];
        #pragma unroll
        for (int i = 0; i < RN; i++) {
            float y = ybase[(size_t)i * G + g];
            s[i] += y;
            float lu = m + xs[i][0] * b0 + xs[i][1] * b1
                         + xs[i][2] * b2 + xs[i][3] * b3;
            e[i] += __expf(lu);
        }
    }
    #pragma unroll
    for (int o = 16; o; o >>= 1) {
        #pragma unroll
        for (int i = 0; i < RN; i++) {
            s[i] += __shfl_down_sync(0xffffffffu, s[i], o);
            e[i] += __shfl_down_sync(0xffffffffu, e[i], o);
        }
    }
    int lid = t & 31, wid = t >> 5;
    if (lid == 0) {
        #pragma unroll
        for (int i = 0; i < RN; i++) {
            red[wid][i]      = s[i];
            red[wid][RN + i] = e[i];
        }
    }
    __syncthreads();
    if (t < RN) {
        float S = 0.0f, E = 0.0f;
        #pragma unroll
        for (int w = 0; w < 8; w++) { S += red[w][t]; E += red[w][RN + t]; }
        d_sp[(n0 + t) * GS + chunk] = S;
        d_ep[(n0 + t) * GS + chunk] = E;
    }
}

// -------------------- kernel 3: main NB log-lik + final reduction ----------
// 512 genes x 32 rows per block; 2 genes x 4 rows per iteration.
__global__ __launch_bounds__(256, 4) void k_main(
        const float4* __restrict__ X4, const float* __restrict__ Y,
        const float* __restrict__ mu, const float* __restrict__ beta,
        int N, int G, int nbp, int nbk, float* __restrict__ out) {
    __shared__ float4 xs4[TN];
    __shared__ float  as[TN];
    __shared__ float  lf[512];
    __shared__ double sw[8];
    __shared__ int    sflag;

    int t  = threadIdx.x;
    int g0 = blockIdx.x * 512 + 2 * t;   // genes g0, g0+1
    int n0 = blockIdx.y * TN;

    if (t < TN) {
        xs4[t] = X4[n0 + t];
        float S = 0.0f, E = 0.0f;
        #pragma unroll
        for (int c = 0; c < GS; c++) {
            S += d_sp[(n0 + t) * GS + c];
            E += d_ep[(n0 + t) * GS + c];
        }
        as[t] = logf(S) - logf(E);
    }
    for (int i = t; i < 512; i += 256) lf[i] = d_lft[i];
    __syncthreads();

    float accA = 0.0f, accB = 0.0f, accC = 0.0f, accD = 0.0f;
    if (g0 + 1 < G) {
        float2 mug = *(const float2*)(mu + g0);
        float2 B0  = *(const float2*)(beta + g0);
        float2 B1  = *(const float2*)(beta + G + g0);
        float2 B2  = *(const float2*)(beta + 2 * G + g0);
        float2 B3  = *(const float2*)(beta + 3 * G + g0);
        float2 R   = *(const float2*)(d_r + g0);
        float2 C   = *(const float2*)(d_c + g0);
        const float* yp = Y + (size_t)n0 * G + g0;
        const float ST = 0.918938533204673f;  // 0.5*log(2*pi)

        #pragma unroll 2
        for (int i = 0; i < TN; i += 4) {
            // 4 independent row loads batched up front (MLP)
            float2 y0 = *(const float2*)yp;
            float2 y1 = *(const float2*)(yp + G);
            float2 y2 = *(const float2*)(yp + 2 * (size_t)G);
            float2 y3 = *(const float2*)(yp + 3 * (size_t)G);
            yp += 4 * (size_t)G;

            #pragma unroll
            for (int j = 0; j < 4; j++) {
                float2 yy = (j == 0) ? y0 : (j == 1) ? y1 : (j == 2) ? y2 : y3;
                float4 x  = xs4[i + j];
                float an  = as[i + j];

                float luA = mug.x + x.x*B0.x + x.y*B1.x + x.z*B2.x + x.w*B3.x;
                float luB = mug.y + x.x*B0.y + x.y*B1.y + x.z*B2.y + x.w*B3.y;
                float vA = luA + an, vB = luB + an;
                float mA = __expf(vA), mB = __expf(vB);
                float zA = yy.x + R.x, zB = yy.y + R.y;

                float lgA = fmaf(zA - 0.5f, __logf(zA), -zA) + ST
                          + 0.08333333333f * frcp_approx(zA) - lf[(int)yy.x];
                float lgB = fmaf(zB - 0.5f, __logf(zB), -zB) + ST
                          + 0.08333333333f * frcp_approx(zB) - lf[(int)yy.y];
                if (yy.x < 7.5f) lgA = d_small[(int)yy.x * G + g0];
                if (yy.y < 7.5f) lgB = d_small[(int)yy.y * G + g0 + 1];

                float tA = __logf(R.x + mA), tB = __logf(R.y + mB);
                if (j & 1) {
                    accC += lgA + fmaf(yy.x, vA, -zA * tA);
                    accD += lgB + fmaf(yy.y, vB, -zB * tB);
                } else {
                    accA += lgA + fmaf(yy.x, vA, -zA * tA);
                    accB += lgB + fmaf(yy.y, vB, -zB * tB);
                }
            }
        }
        accA += (C.x + C.y) * (float)TN;
    }
    double w = warp_red_d(((double)accA + (double)accB) + ((double)accC + (double)accD));
    int lid = t & 31, wid = t >> 5;
    if (lid == 0) sw[wid] = w;
    __syncthreads();
    int bid = blockIdx.y * gridDim.x + blockIdx.x;
    if (wid == 0) {
        double v = (lid < 8) ? sw[lid] : 0.0;
        v = warp_red_d(v);
        if (lid == 0) d_part[1024 + bid] = v;
    }
    // last-block deterministic final reduction
    if (t == 0) {
        __threadfence();
        int v = atomicAdd(&d_cnt, 1);
        sflag = (v == nbk - 1);
    }
    __syncthreads();
    if (sflag) {
        __threadfence();
        double s = 0.0;
        for (int i = t; i < nbp; i += 256) s += d_part[i];
        for (int i = t; i < nbk; i += 256) s += d_part[1024 + i];
        double ww = warp_red_d(s);
        if (lid == 0) sw[wid] = ww;
        __syncthreads();
        if (wid == 0) {
            double v = (lid < 8) ? sw[lid] : 0.0;
            v = warp_red_d(v);
            if (lid == 0) { out[0] = (float)v; d_cnt = 0; }
        }
    }
}

// ---------------------------------------------------------------------------
extern "C" void kernel_launch(void* const* d_in, const int* in_sizes, int n_in,
                              void* d_out, int out_size) {
    const float* X    = (const float*)d_in[0];
    const float* Y    = (const float*)d_in[1];
    const float* mu   = (const float*)d_in[2];
    const float* beta = (const float*)d_in[3];
    const float* phi  = (const float*)d_in[4];
    int G = in_sizes[2];
    int N = in_sizes[1] / G;
    int P = in_sizes[0] / N;
    float* out = (float*)d_out;

    int nbp = (G + 127) / 128;
    k_perg<<<nbp, 128>>>(mu, beta, phi, G, P);
    k_rowA<<<dim3(GS, (N + RN - 1) / RN), 256>>>(X, Y, mu, beta, G);
    int nbx = (G + 511) / 512;
    int nby = (N + TN - 1) / TN;
    k_main<<<dim3(nbx, nby), 256>>>((const float4*)X, Y, mu, beta,
                                    N, G, nbp, nbx * nby, out);
}

// round 8
// speedup vs baseline: 1.2084x; 1.2084x over previous
#include <cuda_runtime.h>
#include <math.h>

// ---------------------------------------------------------------------------
// NB regression log-posterior. 3 launches:
//  k_perg : lgamma tables via recurrence (1 lgammaf/gene), priors -> d_part
//  k_rowA : gene-chunked single-pass  s_n = sum(Y[n,:]) and sumexp(mu+X beta)
//  k_main : per-block a_n recompute + 20.5M-element NB log-lik
//           (2 genes x 2 rows per iteration), last-block final reduction.
// ---------------------------------------------------------------------------

#define GMAX  20480
#define NMAX  4096
#define NPART 4096
#define TN    32       // rows per k_main block
#define RN    4        // rows per k_rowA block
#define GS    8        // gene chunks in k_rowA

__device__ float  d_r[GMAX];
__device__ float  d_c[GMAX];
__device__ float  d_lft[512];
__device__ float  d_small[8 * GMAX];     // [y][g] : lgamma(y+r)-lgamma(y+1)
__device__ float  d_sp[NMAX * GS];       // library-size partials [n][chunk]
__device__ float  d_ep[NMAX * GS];       // sumexp partials       [n][chunk]
__device__ double d_part[NPART];
__device__ int    d_cnt = 0;

__device__ __forceinline__ float frcp_approx(float x) {
    float r; asm("rcp.approx.f32 %0, %1;" : "=f"(r) : "f"(x)); return r;
}

__device__ __forceinline__ double warp_red_d(double v) {
    #pragma unroll
    for (int o = 16; o; o >>= 1) v += __shfl_down_sync(0xffffffffu, v, o);
    return v;
}

// -------------------- kernel 1: tables + per-gene precompute + priors ------
__global__ __launch_bounds__(128) void k_perg(
        const float* __restrict__ mu, const float* __restrict__ beta,
        const float* __restrict__ phi, int G, int P) {
    __shared__ double sw[4];
    int g = blockIdx.x * 128 + threadIdx.x;
    if (g < 512) d_lft[g] = lgammaf((float)g + 1.0f);
    double loc = 0.0;
    if (g < G) {
        float ph = phi[g];
        float sp = fmaxf(ph, 0.0f) + log1pf(expf(-fabsf(ph)));  // softplus
        float r  = 1.0f / sp;
        d_r[g] = r;
        float lg_r = lgammaf(r);
        d_c[g] = r * logf(r) - lg_r;
        // lgamma(y+1) for y=0..7, exact constants
        const float LFT[8] = {0.0f, 0.0f, 0.6931471805599453f, 1.791759469228055f,
                              3.1780538303479458f, 4.787491742782046f,
                              6.579251212010101f, 8.525161361065415f};
        float acc = lg_r;                       // lgamma(0+r)
        #pragma unroll
        for (int y = 0; y < 8; y++) {
            d_small[y * G + g] = acc - LFT[y];
            acc += __logf(r + (float)y);        // -> lgamma(y+1+r)
        }
        const float C2 = -1.6120857137646180f;  // -0.5*log(2*pi*4)
        float m  = mu[g];
        float pr = C2 - m * m * 0.125f;         // normal prior on mu
        for (int p = 0; p < P; p++) {           // normal prior on beta
            float b = beta[p * G + g];
            pr += C2 - b * b * 0.125f;
        }
        pr += logf(sp) - sp;                    // gamma(2,1) prior: log x - x
        loc = (double)pr;
    }
    double w = warp_red_d(loc);
    int lid = threadIdx.x & 31, wid = threadIdx.x >> 5;
    if (lid == 0) sw[wid] = w;
    __syncthreads();
    if (wid == 0) {
        double v = (lid < 4) ? sw[lid] : 0.0;
        v = warp_red_d(v);
        if (lid == 0) d_part[blockIdx.x] = v;
    }
}

// -------------------- kernel 2: chunked library-size + sumexp partials -----
__global__ __launch_bounds__(256) void k_rowA(
        const float* __restrict__ X, const float* __restrict__ Y,
        const float* __restrict__ mu, const float* __restrict__ beta, int G) {
    __shared__ float xs[RN][4];
    __shared__ float red[8][2 * RN];
    int chunk = blockIdx.x;
    int L  = (G + GS - 1) / GS;
    int c0 = chunk * L;
    int c1 = min(c0 + L, G);
    int n0 = blockIdx.y * RN;
    int t  = threadIdx.x;
    if (t < RN * 4) ((float*)xs)[t] = X[n0 * 4 + t];
    __syncthreads();

    float s[RN], e[RN];
    #pragma unroll
    for (int i = 0; i < RN; i++) { s[i] = 0.0f; e[i] = 0.0f; }

    const float* ybase = Y + (size_t)n0 * G;
    for (int g = c0 + t; g < c1; g += 256) {
        float m  = mu[g];
        float b0 = beta[g];
        float b1 = beta[G + g];
        float b2 = beta[2 * G + g];
        float b3 = beta[3 * G + g];
        #pragma unroll
        for (int i = 0; i < RN; i++) {
            float y = __ldcs(ybase + (size_t)i * G + g);
            s[i] += y;
            float lu = m + xs[i][0] * b0 + xs[i][1] * b1
                         + xs[i][2] * b2 + xs[i][3] * b3;
            e[i] += __expf(lu);
        }
    }
    #pragma unroll
    for (int o = 16; o; o >>= 1) {
        #pragma unroll
        for (int i = 0; i < RN; i++) {
            s[i] += __shfl_down_sync(0xffffffffu, s[i], o);
            e[i] += __shfl_down_sync(0xffffffffu, e[i], o);
        }
    }
    int lid = t & 31, wid = t >> 5;
    if (lid == 0) {
        #pragma unroll
        for (int i = 0; i < RN; i++) {
            red[wid][i]      = s[i];
            red[wid][RN + i] = e[i];
        }
    }
    __syncthreads();
    if (t < RN) {
        float S = 0.0f, E = 0.0f;
        #pragma unroll
        for (int w = 0; w < 8; w++) { S += red[w][t]; E += red[w][RN + t]; }
        d_sp[(n0 + t) * GS + chunk] = S;
        d_ep[(n0 + t) * GS + chunk] = E;
    }
}

// -------------------- kernel 3: main NB log-lik + final reduction ----------
// 512 genes x 32 rows per block; 2 genes x 2 rows per thread-iteration.
__global__ __launch_bounds__(256, 4) void k_main(
        const float4* __restrict__ X4, const float* __restrict__ Y,
        const float* __restrict__ mu, const float* __restrict__ beta,
        int N, int G, int nbp, int nbk, float* __restrict__ out) {
    __shared__ float4 xs4[TN];
    __shared__ float  as[TN];
    __shared__ float  lf[512];
    __shared__ double sw[8];
    __shared__ int    sflag;

    int t  = threadIdx.x;
    int g0 = blockIdx.x * 512 + 2 * t;   // genes g0, g0+1
    int n0 = blockIdx.y * TN;

    if (t < TN) {
        xs4[t] = X4[n0 + t];
        float S = 0.0f, E = 0.0f;
        #pragma unroll
        for (int c = 0; c < GS; c++) {
            S += d_sp[(n0 + t) * GS + c];
            E += d_ep[(n0 + t) * GS + c];
        }
        as[t] = logf(S) - logf(E);
    }
    for (int i = t; i < 512; i += 256) lf[i] = d_lft[i];
    __syncthreads();

    float accA = 0.0f, accB = 0.0f, accC = 0.0f, accD = 0.0f;
    if (g0 + 1 < G) {
        float2 mug = *(const float2*)(mu + g0);
        float2 B0  = *(const float2*)(beta + g0);
        float2 B1  = *(const float2*)(beta + G + g0);
        float2 B2  = *(const float2*)(beta + 2 * G + g0);
        float2 B3  = *(const float2*)(beta + 3 * G + g0);
        float2 R   = *(const float2*)(d_r + g0);
        float2 C   = *(const float2*)(d_c + g0);
        const float2* yp = (const float2*)(Y + (size_t)n0 * G + g0);
        size_t G2 = (size_t)G / 2;
        const float ST = 0.918938533204673f;  // 0.5*log(2*pi)

        #pragma unroll 2
        for (int i = 0; i < TN; i += 2) {
            float2 ya = __ldcs(yp);
            float2 yb = __ldcs(yp + G2);
            yp += 2 * G2;
            float4 xa = xs4[i], xb = xs4[i + 1];
            float ana = as[i], anb = as[i + 1];

            float luA = mug.x + xa.x*B0.x + xa.y*B1.x + xa.z*B2.x + xa.w*B3.x;
            float luB = mug.y + xa.x*B0.y + xa.y*B1.y + xa.z*B2.y + xa.w*B3.y;
            float luC = mug.x + xb.x*B0.x + xb.y*B1.x + xb.z*B2.x + xb.w*B3.x;
            float luD = mug.y + xb.x*B0.y + xb.y*B1.y + xb.z*B2.y + xb.w*B3.y;
            float vA = luA + ana, vB = luB + ana, vC = luC + anb, vD = luD + anb;
            float mA = __expf(vA), mB = __expf(vB), mC = __expf(vC), mD = __expf(vD);
            float zA = ya.x + R.x, zB = ya.y + R.y, zC = yb.x + R.x, zD = yb.y + R.y;

            float lgA = fmaf(zA - 0.5f, __logf(zA), -zA) + ST + 0.08333333333f * frcp_approx(zA);
            float lgB = fmaf(zB - 0.5f, __logf(zB), -zB) + ST + 0.08333333333f * frcp_approx(zB);
            float lgC = fmaf(zC - 0.5f, __logf(zC), -zC) + ST + 0.08333333333f * frcp_approx(zC);
            float lgD = fmaf(zD - 0.5f, __logf(zD), -zD) + ST + 0.08333333333f * frcp_approx(zD);
            lgA -= lf[(int)ya.x];  lgB -= lf[(int)ya.y];
            lgC -= lf[(int)yb.x];  lgD -= lf[(int)yb.y];
            if (ya.x < 7.5f) lgA = d_small[(int)ya.x * G + g0];
            if (ya.y < 7.5f) lgB = d_small[(int)ya.y * G + g0 + 1];
            if (yb.x < 7.5f) lgC = d_small[(int)yb.x * G + g0];
            if (yb.y < 7.5f) lgD = d_small[(int)yb.y * G + g0 + 1];

            float tA = __logf(R.x + mA), tB = __logf(R.y + mB);
            float tC = __logf(R.x + mC), tD = __logf(R.y + mD);
            accA += lgA + fmaf(ya.x, vA, -zA * tA);
            accB += lgB + fmaf(ya.y, vB, -zB * tB);
            accC += lgC + fmaf(yb.x, vC, -zC * tC);
            accD += lgD + fmaf(yb.y, vD, -zD * tD);
        }
        accA += (C.x + C.y) * (float)TN;
    }
    double w = warp_red_d(((double)accA + (double)accB) + ((double)accC + (double)accD));
    int lid = t & 31, wid = t >> 5;
    if (lid == 0) sw[wid] = w;
    __syncthreads();
    int bid = blockIdx.y * gridDim.x + blockIdx.x;
    if (wid == 0) {
        double v = (lid < 8) ? sw[lid] : 0.0;
        v = warp_red_d(v);
        if (lid == 0) d_part[1024 + bid] = v;
    }
    // last-block deterministic final reduction
    if (t == 0) {
        __threadfence();
        int v = atomicAdd(&d_cnt, 1);
        sflag = (v == nbk - 1);
    }
    __syncthreads();
    if (sflag) {
        __threadfence();
        double s = 0.0;
        for (int i = t; i < nbp; i += 256) s += d_part[i];
        for (int i = t; i < nbk; i += 256) s += d_part[1024 + i];
        double ww = warp_red_d(s);
        if (lid == 0) sw[wid] = ww;
        __syncthreads();
        if (wid == 0) {
            double v = (lid < 8) ? sw[lid] : 0.0;
            v = warp_red_d(v);
            if (lid == 0) { out[0] = (float)v; d_cnt = 0; }
        }
    }
}

// ---------------------------------------------------------------------------
extern "C" void kernel_launch(void* const* d_in, const int* in_sizes, int n_in,
                              void* d_out, int out_size) {
    const float* X    = (const float*)d_in[0];
    const float* Y    = (const float*)d_in[1];
    const float* mu   = (const float*)d_in[2];
    const float* beta = (const float*)d_in[3];
    const float* phi  = (const float*)d_in[4];
    int G = in_sizes[2];
    int N = in_sizes[1] / G;
    int P = in_sizes[0] / N;
    float* out = (float*)d_out;

    int nbp = (G + 127) / 128;
    k_perg<<<nbp, 128>>>(mu, beta, phi, G, P);
    k_rowA<<<dim3(GS, (N + RN - 1) / RN), 256>>>(X, Y, mu, beta, G);
    int nbx = (G + 511) / 512;
    int nby = (N + TN - 1) / TN;
    k_main<<<dim3(nbx, nby), 256>>>((const float4*)X, Y, mu, beta,
                                    N, G, nbp, nbx * nby, out);
}

// round 10
// speedup vs baseline: 1.2947x; 1.0714x over previous
#include <cuda_runtime.h>
#include <math.h>

// ---------------------------------------------------------------------------
// NB regression log-posterior. 2 launches:
//  k_pre  : fused grid — columns [0,GS) do gene-chunked single-pass
//           s_n = sum(Y[n,:]) and sumexp(mu+X beta) partials;
//           column GS does per-gene lgamma tables (recurrence) + priors.
//           The MUFU-heavy gene work overlaps the memory-bound row work.
//  k_main : per-block a_n recompute + 20.5M-element NB log-lik
//           (2 genes x 2 rows per iteration), last-block final reduction.
// ---------------------------------------------------------------------------

#define GMAX  20480
#define NMAX  4096
#define NPART 4096
#define TN    32       // rows per k_main block
#define RN    4        // rows per k_pre row-block
#define GS    8        // gene chunks for row work

__device__ float  d_r[GMAX];
__device__ float  d_c[GMAX];
__device__ float  d_lft[512];
__device__ float  d_small[8 * GMAX];     // [y][g] : lgamma(y+r)-lgamma(y+1)
__device__ float  d_sp[NMAX * GS];       // library-size partials [n][chunk]
__device__ float  d_ep[NMAX * GS];       // sumexp partials       [n][chunk]
__device__ double d_part[NPART];
__device__ int    d_cnt = 0;

__device__ __forceinline__ float frcp_approx(float x) {
    float r; asm("rcp.approx.f32 %0, %1;" : "=f"(r) : "f"(x)); return r;
}

__device__ __forceinline__ double warp_red_d(double v) {
    #pragma unroll
    for (int o = 16; o; o >>= 1) v += __shfl_down_sync(0xffffffffu, v, o);
    return v;
}

// -------------------- kernel 1: fused row partials + gene precompute -------
__global__ __launch_bounds__(256) void k_pre(
        const float* __restrict__ X, const float* __restrict__ Y,
        const float* __restrict__ mu, const float* __restrict__ beta,
        const float* __restrict__ phi, int G, int P) {
    int t = threadIdx.x;

    if (blockIdx.x == GS) {
        // ---------------- per-gene precompute + priors ----------------
        __shared__ double sw[8];
        int g = blockIdx.y * 256 + t;
        if (g < 512) d_lft[g] = lgammaf((float)g + 1.0f);
        double loc = 0.0;
        if (g < G) {
            float ph = phi[g];
            float sp = fmaxf(ph, 0.0f) + log1pf(expf(-fabsf(ph)));  // softplus
            float r  = 1.0f / sp;
            d_r[g] = r;
            float lg_r = lgammaf(r);
            d_c[g] = r * logf(r) - lg_r;
            const float LFT[8] = {0.0f, 0.0f, 0.6931471805599453f, 1.791759469228055f,
                                  3.1780538303479458f, 4.787491742782046f,
                                  6.579251212010101f, 8.525161361065415f};
            float acc = lg_r;                       // lgamma(0+r)
            #pragma unroll
            for (int y = 0; y < 8; y++) {
                d_small[y * G + g] = acc - LFT[y];
                acc += __logf(r + (float)y);        // -> lgamma(y+1+r)
            }
            const float C2 = -1.6120857137646180f;  // -0.5*log(2*pi*4)
            float m  = mu[g];
            float pr = C2 - m * m * 0.125f;         // normal prior on mu
            for (int p = 0; p < P; p++) {           // normal prior on beta
                float b = beta[p * G + g];
                pr += C2 - b * b * 0.125f;
            }
            pr += logf(sp) - sp;                    // gamma(2,1): log x - x
            loc = (double)pr;
        }
        double w = warp_red_d(loc);
        int lid = t & 31, wid = t >> 5;
        if (lid == 0) sw[wid] = w;
        __syncthreads();
        if (wid == 0) {
            double v = (lid < 8) ? sw[lid] : 0.0;
            v = warp_red_d(v);
            if (lid == 0) d_part[blockIdx.y] = v;
        }
        return;
    }

    // ---------------- row partials: library size + sumexp ----------------
    __shared__ float xs[RN][4];
    __shared__ float red[8][2 * RN];
    int chunk = blockIdx.x;
    int L  = (G + GS - 1) / GS;
    int c0 = chunk * L;
    int c1 = min(c0 + L, G);
    int n0 = blockIdx.y * RN;
    if (t < RN * 4) ((float*)xs)[t] = X[n0 * 4 + t];
    __syncthreads();

    float s[RN], e[RN];
    #pragma unroll
    for (int i = 0; i < RN; i++) { s[i] = 0.0f; e[i] = 0.0f; }

    const float* ybase = Y + (size_t)n0 * G;
    for (int g = c0 + t; g < c1; g += 256) {
        float m  = mu[g];
        float b0 = beta[g];
        float b1 = beta[G + g];
        float b2 = beta[2 * G + g];
        float b3 = beta[3 * G + g];
        #pragma unroll
        for (int i = 0; i < RN; i++) {
            float y = ybase[(size_t)i * G + g];
            s[i] += y;
            float lu = m + xs[i][0] * b0 + xs[i][1] * b1
                         + xs[i][2] * b2 + xs[i][3] * b3;
            e[i] += __expf(lu);
        }
    }
    #pragma unroll
    for (int o = 16; o; o >>= 1) {
        #pragma unroll
        for (int i = 0; i < RN; i++) {
            s[i] += __shfl_down_sync(0xffffffffu, s[i], o);
            e[i] += __shfl_down_sync(0xffffffffu, e[i], o);
        }
    }
    int lid = t & 31, wid = t >> 5;
    if (lid == 0) {
        #pragma unroll
        for (int i = 0; i < RN; i++) {
            red[wid][i]      = s[i];
            red[wid][RN + i] = e[i];
        }
    }
    __syncthreads();
    if (t < RN) {
        float S = 0.0f, E = 0.0f;
        #pragma unroll
        for (int w = 0; w < 8; w++) { S += red[w][t]; E += red[w][RN + t]; }
        d_sp[(n0 + t) * GS + chunk] = S;
        d_ep[(n0 + t) * GS + chunk] = E;
    }
}

// -------------------- kernel 2: main NB log-lik + final reduction ----------
// 512 genes x 32 rows per block; 2 genes x 2 rows per thread-iteration.
__global__ __launch_bounds__(256, 4) void k_main(
        const float4* __restrict__ X4, const float* __restrict__ Y,
        const float* __restrict__ mu, const float* __restrict__ beta,
        int N, int G, int nbp, int nbk, float* __restrict__ out) {
    __shared__ float4 xs4[TN];
    __shared__ float  as[TN];
    __shared__ float  lf[512];
    __shared__ double sw[8];
    __shared__ int    sflag;

    int t  = threadIdx.x;
    int g0 = blockIdx.x * 512 + 2 * t;   // genes g0, g0+1
    int n0 = blockIdx.y * TN;

    if (t < TN) {
        xs4[t] = X4[n0 + t];
        float S = 0.0f, E = 0.0f;
        #pragma unroll
        for (int c = 0; c < GS; c++) {
            S += d_sp[(n0 + t) * GS + c];
            E += d_ep[(n0 + t) * GS + c];
        }
        as[t] = logf(S) - logf(E);
    }
    for (int i = t; i < 512; i += 256) lf[i] = d_lft[i];
    __syncthreads();

    float accA = 0.0f, accB = 0.0f, accC = 0.0f, accD = 0.0f;
    if (g0 + 1 < G) {
        float2 mug = *(const float2*)(mu + g0);
        float2 B0  = *(const float2*)(beta + g0);
        float2 B1  = *(const float2*)(beta + G + g0);
        float2 B2  = *(const float2*)(beta + 2 * G + g0);
        float2 B3  = *(const float2*)(beta + 3 * G + g0);
        float2 R   = *(const float2*)(d_r + g0);
        float2 C   = *(const float2*)(d_c + g0);
        const float* yp = Y + (size_t)n0 * G + g0;
        const float ST = 0.918938533204673f;  // 0.5*log(2*pi)

        #pragma unroll 2
        for (int i = 0; i < TN; i += 2) {
            float2 ya = *(const float2*)yp;
            float2 yb = *(const float2*)(yp + G);
            yp += 2 * (size_t)G;
            float4 xa = xs4[i], xb = xs4[i + 1];
            float ana = as[i], anb = as[i + 1];

            float luA = mug.x + xa.x*B0.x + xa.y*B1.x + xa.z*B2.x + xa.w*B3.x;
            float luB = mug.y + xa.x*B0.y + xa.y*B1.y + xa.z*B2.y + xa.w*B3.y;
            float luC = mug.x + xb.x*B0.x + xb.y*B1.x + xb.z*B2.x + xb.w*B3.x;
            float luD = mug.y + xb.x*B0.y + xb.y*B1.y + xb.z*B2.y + xb.w*B3.y;
            float vA = luA + ana, vB = luB + ana, vC = luC + anb, vD = luD + anb;
            float mA = __expf(vA), mB = __expf(vB), mC = __expf(vC), mD = __expf(vD);
            float zA = ya.x + R.x, zB = ya.y + R.y, zC = yb.x + R.x, zD = yb.y + R.y;

            float lgA = fmaf(zA - 0.5f, __logf(zA), -zA) + ST + 0.08333333333f * frcp_approx(zA);
            float lgB = fmaf(zB - 0.5f, __logf(zB), -zB) + ST + 0.08333333333f * frcp_approx(zB);
            float lgC = fmaf(zC - 0.5f, __logf(zC), -zC) + ST + 0.08333333333f * frcp_approx(zC);
            float lgD = fmaf(zD - 0.5f, __logf(zD), -zD) + ST + 0.08333333333f * frcp_approx(zD);
            lgA -= lf[(int)ya.x];  lgB -= lf[(int)ya.y];
            lgC -= lf[(int)yb.x];  lgD -= lf[(int)yb.y];
            if (ya.x < 7.5f) lgA = d_small[(int)ya.x * G + g0];
            if (ya.y < 7.5f) lgB = d_small[(int)ya.y * G + g0 + 1];
            if (yb.x < 7.5f) lgC = d_small[(int)yb.x * G + g0];
            if (yb.y < 7.5f) lgD = d_small[(int)yb.y * G + g0 + 1];

            float tA = __logf(R.x + mA), tB = __logf(R.y + mB);
            float tC = __logf(R.x + mC), tD = __logf(R.y + mD);
            accA += lgA + fmaf(ya.x, vA, -zA * tA);
            accB += lgB + fmaf(ya.y, vB, -zB * tB);
            accC += lgC + fmaf(yb.x, vC, -zC * tC);
            accD += lgD + fmaf(yb.y, vD, -zD * tD);
        }
        accA += (C.x + C.y) * (float)TN;
    }
    double w = warp_red_d(((double)accA + (double)accB) + ((double)accC + (double)accD));
    int lid = t & 31, wid = t >> 5;
    if (lid == 0) sw[wid] = w;
    __syncthreads();
    int bid = blockIdx.y * gridDim.x + blockIdx.x;
    if (wid == 0) {
        double v = (lid < 8) ? sw[lid] : 0.0;
        v = warp_red_d(v);
        if (lid == 0) d_part[1024 + bid] = v;
    }
    // last-block deterministic final reduction
    if (t == 0) {
        __threadfence();
        int v = atomicAdd(&d_cnt, 1);
        sflag = (v == nbk - 1);
    }
    __syncthreads();
    if (sflag) {
        __threadfence();
        double s = 0.0;
        for (int i = t; i < nbp; i += 256) s += d_part[i];
        for (int i = t; i < nbk; i += 256) s += d_part[1024 + i];
        double ww = warp_red_d(s);
        if (lid == 0) sw[wid] = ww;
        __syncthreads();
        if (wid == 0) {
            double v = (lid < 8) ? sw[lid] : 0.0;
            v = warp_red_d(v);
            if (lid == 0) { out[0] = (float)v; d_cnt = 0; }
        }
    }
}

// ---------------------------------------------------------------------------
extern "C" void kernel_launch(void* const* d_in, const int* in_sizes, int n_in,
                              void* d_out, int out_size) {
    const float* X    = (const float*)d_in[0];
    const float* Y    = (const float*)d_in[1];
    const float* mu   = (const float*)d_in[2];
    const float* beta = (const float*)d_in[3];
    const float* phi  = (const float*)d_in[4];
    int G = in_sizes[2];
    int N = in_sizes[1] / G;
    int P = in_sizes[0] / N;
    float* out = (float*)d_out;

    int nbp = (G + 255) / 256;           // gene-precompute blocks (column GS)
    int nbrow = (N + RN - 1) / RN;       // row-partial blocks per chunk
    int nby = nbrow > nbp ? nbrow : nbp;
    k_pre<<<dim3(GS + 1, nby), 256>>>(X, Y, mu, beta, phi, G, P);
    int nbx = (G + 511) / 512;
    int nbyy = (N + TN - 1) / TN;
    k_main<<<dim3(nbx, nbyy), 256>>>((const float4*)X, Y, mu, beta,
                                     N, G, nbp, nbx * nbyy, out);
}

// round 11
// speedup vs baseline: 1.4335x; 1.1073x over previous
#include <cuda_runtime.h>
#include <math.h>

// ---------------------------------------------------------------------------
// NB regression log-posterior. 2 launches:
//  k_pre  : 1D fused grid, three block roles:
//           [0, N)            : pure library-size rows  s_n = sum(Y[n,:])
//                               (float4, max MLP, DRAM-bound)
//           [N, N+GS*nbrow)   : sumexp(mu + X beta) chunk partials (L2+MUFU)
//           [.., +nbp)        : per-gene lgamma tables + priors
//           DRAM-bound and MUFU-bound work overlap inside one launch.
//  k_main : per-block a_n recompute + 20.5M-element NB log-lik
//           (2 genes x 2 rows per iteration), last-block final reduction.
// ---------------------------------------------------------------------------

#define GMAX  20480
#define NMAX  4096
#define NPART 4096
#define TN    32       // rows per k_main block
#define RN    4        // rows per E-sum block
#define GS    8        // gene chunks for E-sum

__device__ float  d_s[NMAX];             // library sizes s_n
__device__ float  d_r[GMAX];
__device__ float  d_c[GMAX];
__device__ float  d_lft[512];
__device__ float  d_small[8 * GMAX];     // [y][g]: lgamma(y+r)-lgamma(y+1)-ST
__device__ float  d_ep[NMAX * GS];       // sumexp partials [n][chunk]
__device__ double d_part[NPART];
__device__ int    d_cnt = 0;

__device__ __forceinline__ float frcp_approx(float x) {
    float r; asm("rcp.approx.f32 %0, %1;" : "=f"(r) : "f"(x)); return r;
}

__device__ __forceinline__ double warp_red_d(double v) {
    #pragma unroll
    for (int o = 16; o; o >>= 1) v += __shfl_down_sync(0xffffffffu, v, o);
    return v;
}

#define STIR 0.918938533204673f   // 0.5*log(2*pi)

// -------------------- kernel 1: fused pre-pass -----------------------------
__global__ __launch_bounds__(256) void k_pre(
        const float* __restrict__ X, const float* __restrict__ Y,
        const float* __restrict__ mu, const float* __restrict__ beta,
        const float* __restrict__ phi, int N, int G, int P, int nbrow) {
    int t = threadIdx.x;
    int b = blockIdx.x;

    if (b < N) {
        // ---------------- pure library-size row sum (DRAM-bound) ----------
        __shared__ float sred[8];
        const float4* yr = (const float4*)(Y + (size_t)b * G);
        int nq = G >> 2;
        float s = 0.0f;
        #pragma unroll 4
        for (int i = t; i < nq; i += 256) {
            float4 v = yr[i];
            s += (v.x + v.y) + (v.z + v.w);
        }
        for (int g = (nq << 2) + t; g < G; g += 256) s += Y[(size_t)b * G + g];
        #pragma unroll
        for (int o = 16; o; o >>= 1) s += __shfl_down_sync(0xffffffffu, s, o);
        int lid = t & 31, wid = t >> 5;
        if (lid == 0) sred[wid] = s;
        __syncthreads();
        if (t == 0) {
            float S = 0.0f;
            #pragma unroll
            for (int w = 0; w < 8; w++) S += sred[w];
            d_s[b] = S;
        }
        return;
    }
    b -= N;

    if (b < GS * nbrow) {
        // ---------------- sumexp chunk partials (L2 + MUFU) ---------------
        __shared__ float xs[RN][4];
        __shared__ float red[8][RN];
        int chunk = b / nbrow;
        int rb    = b - chunk * nbrow;
        int L  = (G + GS - 1) / GS;
        int c0 = chunk * L;
        int c1 = min(c0 + L, G);
        int n0 = rb * RN;
        if (t < RN * 4) ((float*)xs)[t] = X[n0 * 4 + t];
        __syncthreads();

        float e[RN];
        #pragma unroll
        for (int i = 0; i < RN; i++) e[i] = 0.0f;

        for (int g = c0 + t; g < c1; g += 256) {
            float m  = mu[g];
            float b0 = beta[g];
            float b1 = beta[G + g];
            float b2 = beta[2 * G + g];
            float b3 = beta[3 * G + g];
            #pragma unroll
            for (int i = 0; i < RN; i++) {
                float lu = m + xs[i][0] * b0 + xs[i][1] * b1
                             + xs[i][2] * b2 + xs[i][3] * b3;
                e[i] += __expf(lu);
            }
        }
        #pragma unroll
        for (int o = 16; o; o >>= 1) {
            #pragma unroll
            for (int i = 0; i < RN; i++)
                e[i] += __shfl_down_sync(0xffffffffu, e[i], o);
        }
        int lid = t & 31, wid = t >> 5;
        if (lid == 0) {
            #pragma unroll
            for (int i = 0; i < RN; i++) red[wid][i] = e[i];
        }
        __syncthreads();
        if (t < RN) {
            float E = 0.0f;
            #pragma unroll
            for (int w = 0; w < 8; w++) E += red[w][t];
            d_ep[(n0 + t) * GS + chunk] = E;
        }
        return;
    }
    b -= GS * nbrow;

    // ---------------- per-gene precompute + priors ------------------------
    __shared__ double sw[8];
    int g = b * 256 + t;
    if (g < 512) d_lft[g] = lgammaf((float)g + 1.0f);
    double loc = 0.0;
    if (g < G) {
        float ph = phi[g];
        float sp = fmaxf(ph, 0.0f) + log1pf(expf(-fabsf(ph)));  // softplus
        float r  = 1.0f / sp;
        d_r[g] = r;
        float lg_r = lgammaf(r);
        d_c[g] = r * logf(r) - lg_r;
        const float LFT[8] = {0.0f, 0.0f, 0.6931471805599453f, 1.791759469228055f,
                              3.1780538303479458f, 4.787491742782046f,
                              6.579251212010101f, 8.525161361065415f};
        float acc = lg_r;                       // lgamma(0+r)
        #pragma unroll
        for (int y = 0; y < 8; y++) {
            d_small[y * G + g] = acc - LFT[y] - STIR;  // pre-subtract hoisted ST
            acc += __logf(r + (float)y);        // -> lgamma(y+1+r)
        }
        const float C2 = -1.6120857137646180f;  // -0.5*log(2*pi*4)
        float m  = mu[g];
        float pr = C2 - m * m * 0.125f;         // normal prior on mu
        for (int p = 0; p < P; p++) {           // normal prior on beta
            float bb = beta[p * G + g];
            pr += C2 - bb * bb * 0.125f;
        }
        pr += logf(sp) - sp;                    // gamma(2,1): log x - x
        loc = (double)pr;
    }
    double w = warp_red_d(loc);
    int lid = t & 31, wid = t >> 5;
    if (lid == 0) sw[wid] = w;
    __syncthreads();
    if (wid == 0) {
        double v = (lid < 8) ? sw[lid] : 0.0;
        v = warp_red_d(v);
        if (lid == 0) d_part[b] = v;
    }
}

// -------------------- kernel 2: main NB log-lik + final reduction ----------
// 512 genes x 32 rows per block; 2 genes x 2 rows per thread-iteration.
__global__ __launch_bounds__(256, 4) void k_main(
        const float4* __restrict__ X4, const float* __restrict__ Y,
        const float* __restrict__ mu, const float* __restrict__ beta,
        int N, int G, int nbp, int nbk, float* __restrict__ out) {
    __shared__ float4 xs4[TN];
    __shared__ float  as[TN];
    __shared__ float  lf[512];
    __shared__ double sw[8];
    __shared__ int    sflag;

    int t  = threadIdx.x;
    int g0 = blockIdx.x * 512 + 2 * t;   // genes g0, g0+1
    int n0 = blockIdx.y * TN;

    if (t < TN) {
        xs4[t] = X4[n0 + t];
        float E = 0.0f;
        #pragma unroll
        for (int c = 0; c < GS; c++) E += d_ep[(n0 + t) * GS + c];
        as[t] = logf(d_s[n0 + t]) - logf(E);
    }
    for (int i = t; i < 512; i += 256) lf[i] = d_lft[i];
    __syncthreads();

    float accA = 0.0f, accB = 0.0f, accC = 0.0f, accD = 0.0f;
    if (g0 + 1 < G) {
        float2 mug = *(const float2*)(mu + g0);
        float2 B0  = *(const float2*)(beta + g0);
        float2 B1  = *(const float2*)(beta + G + g0);
        float2 B2  = *(const float2*)(beta + 2 * G + g0);
        float2 B3  = *(const float2*)(beta + 3 * G + g0);
        float2 R   = *(const float2*)(d_r + g0);
        float2 C   = *(const float2*)(d_c + g0);
        const float* yp = Y + (size_t)n0 * G + g0;

        #pragma unroll 2
        for (int i = 0; i < TN; i += 2) {
            float2 ya = *(const float2*)yp;
            float2 yb = *(const float2*)(yp + G);
            yp += 2 * (size_t)G;
            float4 xa = xs4[i], xb = xs4[i + 1];
            float ana = as[i], anb = as[i + 1];

            float luA = mug.x + xa.x*B0.x + xa.y*B1.x + xa.z*B2.x + xa.w*B3.x;
            float luB = mug.y + xa.x*B0.y + xa.y*B1.y + xa.z*B2.y + xa.w*B3.y;
            float luC = mug.x + xb.x*B0.x + xb.y*B1.x + xb.z*B2.x + xb.w*B3.x;
            float luD = mug.y + xb.x*B0.y + xb.y*B1.y + xb.z*B2.y + xb.w*B3.y;
            float vA = luA + ana, vB = luB + ana, vC = luC + anb, vD = luD + anb;
            float mA = __expf(vA), mB = __expf(vB), mC = __expf(vC), mD = __expf(vD);
            float zA = ya.x + R.x, zB = ya.y + R.y, zC = yb.x + R.x, zD = yb.y + R.y;

            // Stirling with ST hoisted out of the loop (folded into constant)
            float lgA = fmaf(zA - 0.5f, __logf(zA), -zA) + 0.08333333333f * frcp_approx(zA);
            float lgB = fmaf(zB - 0.5f, __logf(zB), -zB) + 0.08333333333f * frcp_approx(zB);
            float lgC = fmaf(zC - 0.5f, __logf(zC), -zC) + 0.08333333333f * frcp_approx(zC);
            float lgD = fmaf(zD - 0.5f, __logf(zD), -zD) + 0.08333333333f * frcp_approx(zD);
            lgA -= lf[(int)ya.x];  lgB -= lf[(int)ya.y];
            lgC -= lf[(int)yb.x];  lgD -= lf[(int)yb.y];
            if (ya.x < 7.5f) lgA = d_small[(int)ya.x * G + g0];
            if (ya.y < 7.5f) lgB = d_small[(int)ya.y * G + g0 + 1];
            if (yb.x < 7.5f) lgC = d_small[(int)yb.x * G + g0];
            if (yb.y < 7.5f) lgD = d_small[(int)yb.y * G + g0 + 1];

            float tA = __logf(R.x + mA), tB = __logf(R.y + mB);
            float tC = __logf(R.x + mC), tD = __logf(R.y + mD);
            accA += lgA + fmaf(ya.x, vA, -zA * tA);
            accB += lgB + fmaf(ya.y, vB, -zB * tB);
            accC += lgC + fmaf(yb.x, vC, -zC * tC);
            accD += lgD + fmaf(yb.y, vD, -zD * tD);
        }
        accA += (C.x + C.y + 2.0f * STIR) * (float)TN;
    }
    double w = warp_red_d(((double)accA + (double)accB) + ((double)accC + (double)accD));
    int lid = t & 31, wid = t >> 5;
    if (lid == 0) sw[wid] = w;
    __syncthreads();
    int bid = blockIdx.y * gridDim.x + blockIdx.x;
    if (wid == 0) {
        double v = (lid < 8) ? sw[lid] : 0.0;
        v = warp_red_d(v);
        if (lid == 0) d_part[1024 + bid] = v;
    }
    // last-block deterministic final reduction
    if (t == 0) {
        __threadfence();
        int v = atomicAdd(&d_cnt, 1);
        sflag = (v == nbk - 1);
    }
    __syncthreads();
    if (sflag) {
        __threadfence();
        double s = 0.0;
        for (int i = t; i < nbp; i += 256) s += d_part[i];
        for (int i = t; i < nbk; i += 256) s += d_part[1024 + i];
        double ww = warp_red_d(s);
        if (lid == 0) sw[wid] = ww;
        __syncthreads();
        if (wid == 0) {
            double v = (lid < 8) ? sw[lid] : 0.0;
            v = warp_red_d(v);
            if (lid == 0) { out[0] = (float)v; d_cnt = 0; }
        }
    }
}

// ---------------------------------------------------------------------------
extern "C" void kernel_launch(void* const* d_in, const int* in_sizes, int n_in,
                              void* d_out, int out_size) {
    const float* X    = (const float*)d_in[0];
    const float* Y    = (const float*)d_in[1];
    const float* mu   = (const float*)d_in[2];
    const float* beta = (const float*)d_in[3];
    const float* phi  = (const float*)d_in[4];
    int G = in_sizes[2];
    int N = in_sizes[1] / G;
    int P = in_sizes[0] / N;
    float* out = (float*)d_out;

    int nbp   = (G + 255) / 256;         // gene-precompute blocks
    int nbrow = (N + RN - 1) / RN;       // E-sum row-blocks per chunk
    int total = N + GS * nbrow + nbp;
    k_pre<<<total, 256>>>(X, Y, mu, beta, phi, N, G, P, nbrow);
    int nbx = (G + 511) / 512;
    int nby = (N + TN - 1) / TN;
    k_main<<<dim3(nbx, nby), 256>>>((const float4*)X, Y, mu, beta,
                                    N, G, nbp, nbx * nby, out);
}